// round 7
// baseline (speedup 1.0000x reference)
#include <cuda_runtime.h>

#define D 128
#define D4 (D / 4)
#define EPS 1e-12f
#define MAX_NODES 50000
#define MAX_EDGES 600000

// ---------------- device scratch (allocation-free) ----------------
__device__ int   g_is64;
__device__ __align__(16) float g_sim_arr[MAX_EDGES];   // sim by original edge id
__device__ int   g_cnt[MAX_NODES];                     // in-degree
__device__ int   g_cursor[MAX_NODES];                  // binning cursors
__device__ int   g_rowstart[MAX_NODES];                // CSR row starts
__device__ __align__(8)  int2  g_epack[MAX_EDGES];     // CSR payload: {src, sim bits}
__device__ __align__(16) float g_x1[(size_t)MAX_NODES * D];

// -------- init: zero counters + index-dtype detection (fused) ---------------
// Reference does .astype(jnp.int64); without jax x64 it stays int32. Detect:
// int64 interpretation of first 32 entries must all be in [0, nn).
__global__ void init_k(const void* __restrict__ ei, int E, int nn) {
    int i = blockIdx.x * blockDim.x + threadIdx.x;
    if (i < nn) { g_cnt[i] = 0; g_cursor[i] = 0; }
    if (blockIdx.x == 0 && threadIdx.x < 32) {
        const long long* p = (const long long*)ei;
        long long v = p[threadIdx.x];            // 32 independent loads
        int bad = (v < 0) || (v >= (long long)nn);
        unsigned m = __ballot_sync(0xffffffffu, bad);
        if (threadIdx.x == 0) g_is64 = (m == 0);
    }
}

__device__ __forceinline__ int load_idx(const void* __restrict__ ei, int e, int E, int which) {
    if (g_is64) return (int)(((const long long*)ei)[(long long)which * E + e]);
    return ((const int*)ei)[which * E + e];
}

// ------- edge similarity + in-degree histogram (warp / 4 edges, MLP=4) ------
// (proven round-4/6 configuration)
__global__ void sim_deg_k(const float4* __restrict__ ea, const float4* __restrict__ q,
                          const void* __restrict__ ei, int E) {
    int t    = blockIdx.x * blockDim.x + threadIdx.x;
    int warp = t >> 5;
    int lane = t & 31;
    int e0   = warp * 4;
    if (e0 >= E) return;

    float4 qq = q[lane];
    float  qn = qq.x*qq.x + qq.y*qq.y + qq.z*qq.z + qq.w*qq.w;

    float dq[4], da[4];
#pragma unroll
    for (int j = 0; j < 4; ++j) {
        int e = e0 + j;
        float4 a = (e < E) ? ea[(long long)e * D4 + lane] : make_float4(0.f,0.f,0.f,0.f);
        dq[j] = a.x*qq.x + a.y*qq.y + a.z*qq.z + a.w*qq.w;
        da[j] = a.x*a.x  + a.y*a.y  + a.z*a.z  + a.w*a.w;
    }

#pragma unroll
    for (int o = 16; o; o >>= 1) {
        qn += __shfl_xor_sync(0xffffffffu, qn, o);
#pragma unroll
        for (int j = 0; j < 4; ++j) {
            dq[j] += __shfl_xor_sync(0xffffffffu, dq[j], o);
            da[j] += __shfl_xor_sync(0xffffffffu, da[j], o);
        }
    }

    if (lane == 0) {
        float qinv = 1.0f / fmaxf(sqrtf(qn), EPS);
#pragma unroll
        for (int j = 0; j < 4; ++j) {
            int e = e0 + j;
            if (e < E) {
                g_sim_arr[e] = dq[j] * qinv / fmaxf(sqrtf(da[j]), EPS);
                atomicAdd(&g_cnt[load_idx(ei, e, E, 1)], 1);
            }
        }
    }
}

// -------- single-block two-pass exclusive scan: g_cnt -> g_rowstart ---------
// Replaces the 3-kernel scan pipeline; saves 2 launches + tiny-kernel ramp.
__global__ void scan_k(int nn) {
    __shared__ int wsum[32];
    int t     = threadIdx.x;
    int lane  = t & 31;
    int wid   = t >> 5;
    int items = (nn + blockDim.x - 1) / blockDim.x;
    int begin = t * items;
    int end   = min(nn, begin + items);

    int sum = 0;
    for (int i = begin; i < end; ++i) sum += g_cnt[i];

    // block-exclusive scan of per-thread sums
    int incl = sum;
#pragma unroll
    for (int o = 1; o < 32; o <<= 1) {
        int tv = __shfl_up_sync(0xffffffffu, incl, o);
        if (lane >= o) incl += tv;
    }
    if (lane == 31) wsum[wid] = incl;
    __syncthreads();
    if (wid == 0) {
        int w  = wsum[lane];
        int wi = w;
#pragma unroll
        for (int o = 1; o < 32; o <<= 1) {
            int tv = __shfl_up_sync(0xffffffffu, wi, o);
            if (lane >= o) wi += tv;
        }
        wsum[lane] = wi - w;
    }
    __syncthreads();
    int run = incl - sum + wsum[wid];

    for (int i = begin; i < end; ++i) {           // counts re-read from L2
        g_rowstart[i] = run;
        run += g_cnt[i];
    }
}

// ------------- bin edges into CSR slots (4 edges/thread, MLP on atomics) ----
__global__ void bin_k(const void* __restrict__ ei, int E) {
    int t  = blockIdx.x * blockDim.x + threadIdx.x;
    int e0 = t * 4;
    if (e0 >= E) return;

    int   s[4], d[4], off[4], rs[4];
    float sm[4];
    int   nv = min(4, E - e0);

#pragma unroll
    for (int j = 0; j < 4; ++j) {              // batch all loads first
        int e = e0 + j;
        if (j < nv) {
            s[j]  = load_idx(ei, e, E, 0);
            d[j]  = load_idx(ei, e, E, 1);
            sm[j] = g_sim_arr[e];
        }
    }
#pragma unroll
    for (int j = 0; j < 4; ++j)                // 4 independent ATOMG in flight
        if (j < nv) off[j] = atomicAdd(&g_cursor[d[j]], 1);
#pragma unroll
    for (int j = 0; j < 4; ++j)
        if (j < nv) rs[j] = g_rowstart[d[j]];
#pragma unroll
    for (int j = 0; j < 4; ++j) {
        if (j < nv) {
            int2 p; p.x = s[j]; p.y = __float_as_int(sm[j]);
            g_epack[rs[j] + off[j]] = p;
        }
    }
}

// -------- gather aggregation + fused residual blend (warp per node) ---------
__global__ void agg_k(const float4* __restrict__ xin, float4* __restrict__ xout, int nn) {
    int t    = blockIdx.x * blockDim.x + threadIdx.x;
    int node = t >> 5;
    int lane = t & 31;
    if (node >= nn) return;

    int start = g_rowstart[node];
    int cnt   = g_cnt[node];
    int end   = start + cnt;

    float accx = 0.f, accy = 0.f, accz = 0.f, accw = 0.f;

    for (int base = start; base < end; base += 32) {
        int n = min(32, end - base);
        int2 mp = (lane < n) ? g_epack[base + lane] : make_int2(0, 0);

        int j = 0;
        for (; j + 8 <= n; j += 8) {
            int s[8]; float m[8]; float4 v[8];
#pragma unroll
            for (int k = 0; k < 8; ++k) {
                s[k] = __shfl_sync(0xffffffffu, mp.x, j + k);
                m[k] = __int_as_float(__shfl_sync(0xffffffffu, mp.y, j + k));
            }
#pragma unroll
            for (int k = 0; k < 8; ++k)     // 8 independent LDG.128 -> MLP=8
                v[k] = xin[(long long)s[k] * D4 + lane];
#pragma unroll
            for (int k = 0; k < 8; ++k) {
                accx += m[k]*v[k].x; accy += m[k]*v[k].y;
                accz += m[k]*v[k].z; accw += m[k]*v[k].w;
            }
        }
        for (; j + 4 <= n; j += 4) {
            int s[4]; float m[4]; float4 v[4];
#pragma unroll
            for (int k = 0; k < 4; ++k) {
                s[k] = __shfl_sync(0xffffffffu, mp.x, j + k);
                m[k] = __int_as_float(__shfl_sync(0xffffffffu, mp.y, j + k));
            }
#pragma unroll
            for (int k = 0; k < 4; ++k)
                v[k] = xin[(long long)s[k] * D4 + lane];
#pragma unroll
            for (int k = 0; k < 4; ++k) {
                accx += m[k]*v[k].x; accy += m[k]*v[k].y;
                accz += m[k]*v[k].z; accw += m[k]*v[k].w;
            }
        }
        for (; j < n; ++j) {
            int   s = __shfl_sync(0xffffffffu, mp.x, j);
            float m = __int_as_float(__shfl_sync(0xffffffffu, mp.y, j));
            float4 v = xin[(long long)s * D4 + lane];
            accx += m*v.x; accy += m*v.y; accz += m*v.z; accw += m*v.w;
        }
    }

    float inv = 0.5f / fmaxf((float)cnt, 1.0f);
    float4 xi = xin[(long long)node * D4 + lane];
    float4 o;
    o.x = 0.5f * xi.x + accx * inv;
    o.y = 0.5f * xi.y + accy * inv;
    o.z = 0.5f * xi.z + accz * inv;
    o.w = 0.5f * xi.w + accw * inv;
    xout[(long long)node * D4 + lane] = o;
}

// ---------------- launch ----------------
extern "C" void kernel_launch(void* const* d_in, const int* in_sizes, int n_in,
                              void* d_out, int out_size) {
    const float* x  = (const float*)d_in[0];
    const float* ea = (const float*)d_in[1];
    const float* q  = (const float*)d_in[2];
    const void*  ei = d_in[3];

    int NN = in_sizes[0] / D;   // 50000
    int E  = in_sizes[3] / 2;   // 600000

    void* x1p = nullptr;
    cudaGetSymbolAddress(&x1p, g_x1);   // address query, capture-safe

    const int TPB = 256;
    int zb      = (NN + TPB - 1) / TPB;
    int simw    = (E + 3) / 4;                       // warps (4 edges each)
    int eb_sim  = (simw * 32 + TPB - 1) / TPB;
    int nthr    = (E + 3) / 4;                       // bin threads (4 edges each)
    int eb_bin  = (nthr + TPB - 1) / TPB;
    int nb_agg  = (NN * 32 + TPB - 1) / TPB;

    init_k   <<<zb, TPB>>>(ei, E, NN);
    sim_deg_k<<<eb_sim, TPB>>>((const float4*)ea, (const float4*)q, ei, E);
    scan_k   <<<1, 1024>>>(NN);
    bin_k    <<<eb_bin, TPB>>>(ei, E);

    // layer 1: x -> g_x1
    agg_k<<<nb_agg, TPB>>>((const float4*)x, (float4*)x1p, NN);
    // layer 2: g_x1 -> d_out
    agg_k<<<nb_agg, TPB>>>((const float4*)x1p, (float4*)d_out, NN);
}

// round 8
// speedup vs baseline: 1.2644x; 1.2644x over previous
#include <cuda_runtime.h>

#define D 128
#define D4 (D / 4)
#define EPS 1e-12f
#define MAX_NODES 50000
#define MAX_EDGES 600000
#define SCAN_B 1024

// ---------------- device scratch (allocation-free) ----------------
__device__ int   g_is64;
__device__ __align__(16) float g_sim_arr[MAX_EDGES];   // sim by original edge id
__device__ int   g_cnt[MAX_NODES];                     // in-degree
__device__ int   g_cursor[MAX_NODES];                  // binning cursors (init = rowstart)
__device__ int   g_rowstart[MAX_NODES];                // CSR row starts
__device__ int   g_blocksums[64];                      // scan partials
__device__ __align__(8)  int2  g_epack[MAX_EDGES];     // CSR payload: {src, sim bits}
__device__ __align__(16) float g_x1[(size_t)MAX_NODES * D];

// -------- init: zero histogram + index-dtype detection (fused) --------------
// Reference does .astype(jnp.int64); without jax x64 it stays int32. Detect:
// int64 interpretation of first 32 entries must all be in [0, nn).
__global__ void init_k(const void* __restrict__ ei, int E, int nn) {
    int i = blockIdx.x * blockDim.x + threadIdx.x;
    if (i < nn) g_cnt[i] = 0;
    if (blockIdx.x == 0 && threadIdx.x < 32) {
        const long long* p = (const long long*)ei;
        long long v = p[threadIdx.x];            // 32 independent loads
        int bad = (v < 0) || (v >= (long long)nn);
        unsigned m = __ballot_sync(0xffffffffu, bad);
        if (threadIdx.x == 0) g_is64 = (m == 0);
    }
}

__device__ __forceinline__ int load_idx(const void* __restrict__ ei, int e, int E, int which) {
    if (g_is64) return (int)(((const long long*)ei)[(long long)which * E + e]);
    return ((const int*)ei)[which * E + e];
}

// ------- edge similarity + in-degree histogram (warp / 4 edges, MLP=4) ------
__global__ void sim_deg_k(const float4* __restrict__ ea, const float4* __restrict__ q,
                          const void* __restrict__ ei, int E) {
    int t    = blockIdx.x * blockDim.x + threadIdx.x;
    int warp = t >> 5;
    int lane = t & 31;
    int e0   = warp * 4;
    if (e0 >= E) return;

    float4 qq = q[lane];
    float  qn = qq.x*qq.x + qq.y*qq.y + qq.z*qq.z + qq.w*qq.w;

    float dq[4], da[4];
#pragma unroll
    for (int j = 0; j < 4; ++j) {
        int e = e0 + j;
        float4 a = (e < E) ? ea[(long long)e * D4 + lane] : make_float4(0.f,0.f,0.f,0.f);
        dq[j] = a.x*qq.x + a.y*qq.y + a.z*qq.z + a.w*qq.w;
        da[j] = a.x*a.x  + a.y*a.y  + a.z*a.z  + a.w*a.w;
    }

#pragma unroll
    for (int o = 16; o; o >>= 1) {
        qn += __shfl_xor_sync(0xffffffffu, qn, o);
#pragma unroll
        for (int j = 0; j < 4; ++j) {
            dq[j] += __shfl_xor_sync(0xffffffffu, dq[j], o);
            da[j] += __shfl_xor_sync(0xffffffffu, da[j], o);
        }
    }

    if (lane == 0) {
        float qinv = 1.0f / fmaxf(sqrtf(qn), EPS);
#pragma unroll
        for (int j = 0; j < 4; ++j) {
            int e = e0 + j;
            if (e < E) {
                g_sim_arr[e] = dq[j] * qinv / fmaxf(sqrtf(da[j]), EPS);
                atomicAdd(&g_cnt[load_idx(ei, e, E, 1)], 1);
            }
        }
    }
}

// ---------------- shuffle-based exclusive scan: g_cnt -> g_rowstart ---------
// (proven round-4/6 3-phase version — lane-contiguous, coalesced, multi-SM)
__global__ void scanA_k(int nn) {
    __shared__ int wsum[32];
    int i    = blockIdx.x * SCAN_B + threadIdx.x;
    int lane = threadIdx.x & 31;
    int wid  = threadIdx.x >> 5;
    int v    = (i < nn) ? g_cnt[i] : 0;

    int incl = v;
#pragma unroll
    for (int o = 1; o < 32; o <<= 1) {
        int tv = __shfl_up_sync(0xffffffffu, incl, o);
        if (lane >= o) incl += tv;
    }
    if (lane == 31) wsum[wid] = incl;
    __syncthreads();
    if (wid == 0) {
        int w  = wsum[lane];
        int wi = w;
#pragma unroll
        for (int o = 1; o < 32; o <<= 1) {
            int tv = __shfl_up_sync(0xffffffffu, wi, o);
            if (lane >= o) wi += tv;
        }
        wsum[lane] = wi - w;                       // exclusive warp offsets
        if (lane == 31) g_blocksums[blockIdx.x] = wi;
    }
    __syncthreads();
    if (i < nn) g_rowstart[i] = incl - v + wsum[wid];
}

__global__ void scanB_k(int nb) {   // <=64 partials, one warp, 2 per lane
    int lane = threadIdx.x;
    int v0 = (2*lane     < nb) ? g_blocksums[2*lane]     : 0;
    int v1 = (2*lane + 1 < nb) ? g_blocksums[2*lane + 1] : 0;
    int s  = v0 + v1;
    int incl = s;
#pragma unroll
    for (int o = 1; o < 32; o <<= 1) {
        int tv = __shfl_up_sync(0xffffffffu, incl, o);
        if (lane >= o) incl += tv;
    }
    int excl = incl - s;
    if (2*lane     < nb) g_blocksums[2*lane]     = excl;
    if (2*lane + 1 < nb) g_blocksums[2*lane + 1] = excl + v0;
}

__global__ void scanC_k(int nn) {
    int i = blockIdx.x * SCAN_B + threadIdx.x;
    if (i < nn) {
        int rs = g_rowstart[i] + g_blocksums[blockIdx.x];
        g_rowstart[i] = rs;
        g_cursor[i]   = rs;          // cursor starts at rowstart -> bin needs 1 atomic only
    }
}

// ------- bin edges into CSR slots (4 edges/thread, single atomic each) ------
__global__ void bin_k(const void* __restrict__ ei, int E) {
    int t  = blockIdx.x * blockDim.x + threadIdx.x;
    int e0 = t * 4;
    if (e0 >= E) return;

    int   s[4], d[4], pos[4];
    float sm[4];
    int   nv = min(4, E - e0);

#pragma unroll
    for (int j = 0; j < 4; ++j) {              // batch all loads first
        int e = e0 + j;
        if (j < nv) {
            s[j]  = load_idx(ei, e, E, 0);
            d[j]  = load_idx(ei, e, E, 1);
            sm[j] = g_sim_arr[e];
        }
    }
#pragma unroll
    for (int j = 0; j < 4; ++j)                // 4 independent ATOMG; pos is absolute
        if (j < nv) pos[j] = atomicAdd(&g_cursor[d[j]], 1);
#pragma unroll
    for (int j = 0; j < 4; ++j) {
        if (j < nv) {
            int2 p; p.x = s[j]; p.y = __float_as_int(sm[j]);
            g_epack[pos[j]] = p;
        }
    }
}

// -------- gather aggregation + fused residual blend (warp per node) ---------
__global__ void agg_k(const float4* __restrict__ xin, float4* __restrict__ xout, int nn) {
    int t    = blockIdx.x * blockDim.x + threadIdx.x;
    int node = t >> 5;
    int lane = t & 31;
    if (node >= nn) return;

    int start = g_rowstart[node];
    int cnt   = g_cnt[node];
    int end   = start + cnt;

    float accx = 0.f, accy = 0.f, accz = 0.f, accw = 0.f;

    for (int base = start; base < end; base += 32) {
        int n = min(32, end - base);
        int2 mp = (lane < n) ? g_epack[base + lane] : make_int2(0, 0);

        int j = 0;
        for (; j + 8 <= n; j += 8) {
            int s[8]; float m[8]; float4 v[8];
#pragma unroll
            for (int k = 0; k < 8; ++k) {
                s[k] = __shfl_sync(0xffffffffu, mp.x, j + k);
                m[k] = __int_as_float(__shfl_sync(0xffffffffu, mp.y, j + k));
            }
#pragma unroll
            for (int k = 0; k < 8; ++k)     // 8 independent LDG.128 -> MLP=8
                v[k] = xin[(long long)s[k] * D4 + lane];
#pragma unroll
            for (int k = 0; k < 8; ++k) {
                accx += m[k]*v[k].x; accy += m[k]*v[k].y;
                accz += m[k]*v[k].z; accw += m[k]*v[k].w;
            }
        }
        for (; j + 4 <= n; j += 4) {
            int s[4]; float m[4]; float4 v[4];
#pragma unroll
            for (int k = 0; k < 4; ++k) {
                s[k] = __shfl_sync(0xffffffffu, mp.x, j + k);
                m[k] = __int_as_float(__shfl_sync(0xffffffffu, mp.y, j + k));
            }
#pragma unroll
            for (int k = 0; k < 4; ++k)
                v[k] = xin[(long long)s[k] * D4 + lane];
#pragma unroll
            for (int k = 0; k < 4; ++k) {
                accx += m[k]*v[k].x; accy += m[k]*v[k].y;
                accz += m[k]*v[k].z; accw += m[k]*v[k].w;
            }
        }
        for (; j < n; ++j) {
            int   s = __shfl_sync(0xffffffffu, mp.x, j);
            float m = __int_as_float(__shfl_sync(0xffffffffu, mp.y, j));
            float4 v = xin[(long long)s * D4 + lane];
            accx += m*v.x; accy += m*v.y; accz += m*v.z; accw += m*v.w;
        }
    }

    float inv = 0.5f / fmaxf((float)cnt, 1.0f);
    float4 xi = xin[(long long)node * D4 + lane];
    float4 o;
    o.x = 0.5f * xi.x + accx * inv;
    o.y = 0.5f * xi.y + accy * inv;
    o.z = 0.5f * xi.z + accz * inv;
    o.w = 0.5f * xi.w + accw * inv;
    xout[(long long)node * D4 + lane] = o;
}

// ---------------- launch ----------------
extern "C" void kernel_launch(void* const* d_in, const int* in_sizes, int n_in,
                              void* d_out, int out_size) {
    const float* x  = (const float*)d_in[0];
    const float* ea = (const float*)d_in[1];
    const float* q  = (const float*)d_in[2];
    const void*  ei = d_in[3];

    int NN = in_sizes[0] / D;   // 50000
    int E  = in_sizes[3] / 2;   // 600000

    void* x1p = nullptr;
    cudaGetSymbolAddress(&x1p, g_x1);   // address query, capture-safe

    const int TPB = 256;
    int zb      = (NN + TPB - 1) / TPB;
    int simw    = (E + 3) / 4;                       // warps (4 edges each)
    int eb_sim  = (simw * 32 + TPB - 1) / TPB;
    int nbscan  = (NN + SCAN_B - 1) / SCAN_B;        // 49 blocks (<=64)
    int nthr    = (E + 3) / 4;                       // bin threads (4 edges each)
    int eb_bin  = (nthr + TPB - 1) / TPB;
    int nb_agg  = (NN * 32 + TPB - 1) / TPB;

    init_k   <<<zb, TPB>>>(ei, E, NN);
    sim_deg_k<<<eb_sim, TPB>>>((const float4*)ea, (const float4*)q, ei, E);

    scanA_k<<<nbscan, SCAN_B>>>(NN);
    scanB_k<<<1, 32>>>(nbscan);
    scanC_k<<<nbscan, SCAN_B>>>(NN);
    bin_k  <<<eb_bin, TPB>>>(ei, E);

    // layer 1: x -> g_x1
    agg_k<<<nb_agg, TPB>>>((const float4*)x, (float4*)x1p, NN);
    // layer 2: g_x1 -> d_out
    agg_k<<<nb_agg, TPB>>>((const float4*)x1p, (float4*)d_out, NN);
}

// round 9
// speedup vs baseline: 1.2942x; 1.0235x over previous
#include <cuda_runtime.h>

#define D 128
#define D4 (D / 4)
#define EPS 1e-12f
#define MAX_NODES 50000
#define MAX_EDGES 600000
#define SCAN_B 1024

// ---------------- device scratch (allocation-free) ----------------
__device__ int   g_is64;
__device__ int   g_total;                              // CSR chunk allocator
__device__ __align__(16) float g_sim_arr[MAX_EDGES];   // sim by original edge id
__device__ int   g_cnt[MAX_NODES];                     // in-degree
__device__ int   g_cursor[MAX_NODES];                  // binning cursors (init = rowstart)
__device__ int   g_rowstart[MAX_NODES];                // CSR row starts
__device__ __align__(8)  int2  g_epack[MAX_EDGES];     // CSR payload: {src, sim bits}
__device__ __align__(16) float g_x1[(size_t)MAX_NODES * D];

// -------- init: zero histogram + allocator + index-dtype detection ----------
// Reference does .astype(jnp.int64); without jax x64 it stays int32. Detect:
// int64 interpretation of first 32 entries must all be in [0, nn).
__global__ void init_k(const void* __restrict__ ei, int E, int nn) {
    int i = blockIdx.x * blockDim.x + threadIdx.x;
    if (i < nn) g_cnt[i] = 0;
    if (i == 0) g_total = 0;
    if (blockIdx.x == 0 && threadIdx.x < 32) {
        const long long* p = (const long long*)ei;
        long long v = p[threadIdx.x];            // 32 independent loads
        int bad = (v < 0) || (v >= (long long)nn);
        unsigned m = __ballot_sync(0xffffffffu, bad);
        if (threadIdx.x == 0) g_is64 = (m == 0);
    }
}

__device__ __forceinline__ int load_idx(const void* __restrict__ ei, int e, int E, int which) {
    if (g_is64) return (int)(((const long long*)ei)[(long long)which * E + e]);
    return ((const int*)ei)[which * E + e];
}

// ------- edge similarity + in-degree histogram (warp / 4 edges, MLP=4) ------
__global__ void sim_deg_k(const float4* __restrict__ ea, const float4* __restrict__ q,
                          const void* __restrict__ ei, int E) {
    int t    = blockIdx.x * blockDim.x + threadIdx.x;
    int warp = t >> 5;
    int lane = t & 31;
    int e0   = warp * 4;
    if (e0 >= E) return;

    float4 qq = q[lane];
    float  qn = qq.x*qq.x + qq.y*qq.y + qq.z*qq.z + qq.w*qq.w;

    float dq[4], da[4];
#pragma unroll
    for (int j = 0; j < 4; ++j) {
        int e = e0 + j;
        float4 a = (e < E) ? ea[(long long)e * D4 + lane] : make_float4(0.f,0.f,0.f,0.f);
        dq[j] = a.x*qq.x + a.y*qq.y + a.z*qq.z + a.w*qq.w;
        da[j] = a.x*a.x  + a.y*a.y  + a.z*a.z  + a.w*a.w;
    }

#pragma unroll
    for (int o = 16; o; o >>= 1) {
        qn += __shfl_xor_sync(0xffffffffu, qn, o);
#pragma unroll
        for (int j = 0; j < 4; ++j) {
            dq[j] += __shfl_xor_sync(0xffffffffu, dq[j], o);
            da[j] += __shfl_xor_sync(0xffffffffu, da[j], o);
        }
    }

    if (lane == 0) {
        float qinv = 1.0f / fmaxf(sqrtf(qn), EPS);
#pragma unroll
        for (int j = 0; j < 4; ++j) {
            int e = e0 + j;
            if (e < E) {
                g_sim_arr[e] = dq[j] * qinv / fmaxf(sqrtf(da[j]), EPS);
                atomicAdd(&g_cnt[load_idx(ei, e, E, 1)], 1);
            }
        }
    }
}

// ----- single-kernel CSR region assignment: block scan + atomic chunk -------
// Row regions need not follow node order — each block reserves a contiguous
// chunk of the edge array via one atomicAdd and lays its nodes inside it.
__global__ void scan_block_k(int nn) {
    __shared__ int wsum[32];
    __shared__ int sbase;
    int i    = blockIdx.x * SCAN_B + threadIdx.x;
    int lane = threadIdx.x & 31;
    int wid  = threadIdx.x >> 5;
    int v    = (i < nn) ? g_cnt[i] : 0;

    int incl = v;                              // warp-inclusive scan
#pragma unroll
    for (int o = 1; o < 32; o <<= 1) {
        int tv = __shfl_up_sync(0xffffffffu, incl, o);
        if (lane >= o) incl += tv;
    }
    if (lane == 31) wsum[wid] = incl;
    __syncthreads();
    if (wid == 0) {
        int w  = wsum[lane];
        int wi = w;
#pragma unroll
        for (int o = 1; o < 32; o <<= 1) {
            int tv = __shfl_up_sync(0xffffffffu, wi, o);
            if (lane >= o) wi += tv;
        }
        wsum[lane] = wi - w;                   // exclusive warp offsets
        if (lane == 31) sbase = atomicAdd(&g_total, wi);   // reserve block chunk
    }
    __syncthreads();
    if (i < nn) {
        int rs = sbase + incl - v + wsum[wid];
        g_rowstart[i] = rs;
        g_cursor[i]   = rs;                    // bin needs a single atomic per edge
    }
}

// ------- bin edges into CSR slots (4 edges/thread, single atomic each) ------
__global__ void bin_k(const void* __restrict__ ei, int E) {
    int t  = blockIdx.x * blockDim.x + threadIdx.x;
    int e0 = t * 4;
    if (e0 >= E) return;

    int   s[4], d[4], pos[4];
    float sm[4];
    int   nv = min(4, E - e0);

#pragma unroll
    for (int j = 0; j < 4; ++j) {              // batch all loads first
        int e = e0 + j;
        if (j < nv) {
            s[j]  = load_idx(ei, e, E, 0);
            d[j]  = load_idx(ei, e, E, 1);
            sm[j] = g_sim_arr[e];
        }
    }
#pragma unroll
    for (int j = 0; j < 4; ++j)                // 4 independent ATOMG; pos is absolute
        if (j < nv) pos[j] = atomicAdd(&g_cursor[d[j]], 1);
#pragma unroll
    for (int j = 0; j < 4; ++j) {
        if (j < nv) {
            int2 p; p.x = s[j]; p.y = __float_as_int(sm[j]);
            g_epack[pos[j]] = p;
        }
    }
}

// -------- gather aggregation + fused residual blend (warp per node) ---------
__global__ void agg_k(const float4* __restrict__ xin, float4* __restrict__ xout, int nn) {
    int t    = blockIdx.x * blockDim.x + threadIdx.x;
    int node = t >> 5;
    int lane = t & 31;
    if (node >= nn) return;

    int start = g_rowstart[node];
    int cnt   = g_cnt[node];
    int end   = start + cnt;

    float accx = 0.f, accy = 0.f, accz = 0.f, accw = 0.f;

    for (int base = start; base < end; base += 32) {
        int n = min(32, end - base);
        int2 mp = (lane < n) ? g_epack[base + lane] : make_int2(0, 0);

        int j = 0;
        for (; j + 8 <= n; j += 8) {
            int s[8]; float m[8]; float4 v[8];
#pragma unroll
            for (int k = 0; k < 8; ++k) {
                s[k] = __shfl_sync(0xffffffffu, mp.x, j + k);
                m[k] = __int_as_float(__shfl_sync(0xffffffffu, mp.y, j + k));
            }
#pragma unroll
            for (int k = 0; k < 8; ++k)     // 8 independent LDG.128 -> MLP=8
                v[k] = xin[(long long)s[k] * D4 + lane];
#pragma unroll
            for (int k = 0; k < 8; ++k) {
                accx += m[k]*v[k].x; accy += m[k]*v[k].y;
                accz += m[k]*v[k].z; accw += m[k]*v[k].w;
            }
        }
        for (; j + 4 <= n; j += 4) {
            int s[4]; float m[4]; float4 v[4];
#pragma unroll
            for (int k = 0; k < 4; ++k) {
                s[k] = __shfl_sync(0xffffffffu, mp.x, j + k);
                m[k] = __int_as_float(__shfl_sync(0xffffffffu, mp.y, j + k));
            }
#pragma unroll
            for (int k = 0; k < 4; ++k)
                v[k] = xin[(long long)s[k] * D4 + lane];
#pragma unroll
            for (int k = 0; k < 4; ++k) {
                accx += m[k]*v[k].x; accy += m[k]*v[k].y;
                accz += m[k]*v[k].z; accw += m[k]*v[k].w;
            }
        }
        for (; j < n; ++j) {
            int   s = __shfl_sync(0xffffffffu, mp.x, j);
            float m = __int_as_float(__shfl_sync(0xffffffffu, mp.y, j));
            float4 v = xin[(long long)s * D4 + lane];
            accx += m*v.x; accy += m*v.y; accz += m*v.z; accw += m*v.w;
        }
    }

    float inv = 0.5f / fmaxf((float)cnt, 1.0f);
    float4 xi = xin[(long long)node * D4 + lane];
    float4 o;
    o.x = 0.5f * xi.x + accx * inv;
    o.y = 0.5f * xi.y + accy * inv;
    o.z = 0.5f * xi.z + accz * inv;
    o.w = 0.5f * xi.w + accw * inv;
    xout[(long long)node * D4 + lane] = o;
}

// ---------------- launch ----------------
extern "C" void kernel_launch(void* const* d_in, const int* in_sizes, int n_in,
                              void* d_out, int out_size) {
    const float* x  = (const float*)d_in[0];
    const float* ea = (const float*)d_in[1];
    const float* q  = (const float*)d_in[2];
    const void*  ei = d_in[3];

    int NN = in_sizes[0] / D;   // 50000
    int E  = in_sizes[3] / 2;   // 600000

    void* x1p = nullptr;
    cudaGetSymbolAddress(&x1p, g_x1);   // address query, capture-safe

    const int TPB = 256;
    int zb      = (NN + TPB - 1) / TPB;
    int simw    = (E + 3) / 4;                       // warps (4 edges each)
    int eb_sim  = (simw * 32 + TPB - 1) / TPB;
    int nbscan  = (NN + SCAN_B - 1) / SCAN_B;        // 49 blocks
    int nthr    = (E + 3) / 4;                       // bin threads (4 edges each)
    int eb_bin  = (nthr + TPB - 1) / TPB;
    int nb_agg  = (NN * 32 + TPB - 1) / TPB;

    init_k      <<<zb, TPB>>>(ei, E, NN);
    sim_deg_k   <<<eb_sim, TPB>>>((const float4*)ea, (const float4*)q, ei, E);
    scan_block_k<<<nbscan, SCAN_B>>>(NN);
    bin_k       <<<eb_bin, TPB>>>(ei, E);

    // layer 1: x -> g_x1
    agg_k<<<nb_agg, TPB>>>((const float4*)x, (float4*)x1p, NN);
    // layer 2: g_x1 -> d_out
    agg_k<<<nb_agg, TPB>>>((const float4*)x1p, (float4*)d_out, NN);
}